// round 1
// baseline (speedup 1.0000x reference)
#include <cuda_runtime.h>
#include <math.h>

#define IMG 96
#define PSZ 8
#define GD 12
#define CDIM 768
#define NHEAD 8
#define HD 96
#define NPATCH 1728
#define NTOK 1729
#define BQ 2
#define NCLS 3

// ---------------- scratch (device globals; no allocation allowed) ----------------
__device__ float g_pat[(size_t)BQ * NPATCH * 512];         // im2col patches
__device__ float g_tmp[(size_t)BQ * NPATCH * CDIM];        // patch-embed GEMM out
__device__ float g_x  [(size_t)BQ * NTOK * CDIM];          // tokens after LN+cls+pos
__device__ float g_q  [(size_t)BQ * NTOK * CDIM];
__device__ float g_k  [(size_t)BQ * NTOK * CDIM];
__device__ float g_v  [(size_t)BQ * NTOK * CDIM];
__device__ float g_S  [(size_t)BQ * NHEAD * NTOK * NTOK];  // attention scores (191MB)
__device__ float g_x2 [(size_t)BQ * NTOK * CDIM];          // regional attn output
__device__ float g_kv [(size_t)BQ * NTOK * 2 * CDIM];      // branch K|V
__device__ float g_q0 [BQ * CDIM];                         // branch q at CLS
__device__ float g_oc [BQ * CDIM];                         // branch attn out at CLS
__device__ float g_fin[BQ * CDIM];                         // weighted branch sum at CLS

// ---------------- generic tiled GEMM: C = alpha*(A?B + bias) (+ C if accum) -------
// TRANS_B=1: C[m,n] = sum_k A[m,k]*B[n,k]   (NT: projections, scores)
// TRANS_B=0: C[m,n] = sum_k A[m,k]*B[k,n]   (NN: attn @ V)
// Batched over gridDim.z; batch z -> (b=z/nh, h=z%nh) with separate b/h strides.
template <int TRANS_B>
__global__ void gemm_k(const float* __restrict__ A, const float* __restrict__ Bm,
                       const float* __restrict__ bias, float* __restrict__ Cm,
                       int M, int Nn, int K, int lda, int ldb, int ldc,
                       size_t sAb, size_t sAh, size_t sBb, size_t sBh,
                       size_t sCb, size_t sCh, int nh,
                       float alphaC, const float* __restrict__ alphaPtr, int accum)
{
    int z = blockIdx.z;
    int bb = z / nh, hh = z % nh;
    A  += (size_t)bb * sAb + (size_t)hh * sAh;
    Bm += (size_t)bb * sBb + (size_t)hh * sBh;
    Cm += (size_t)bb * sCb + (size_t)hh * sCh;

    __shared__ float As[64][17];
    __shared__ float Bs[64][17];
    int tid = threadIdx.x;
    int tx = tid & 15, ty = tid >> 4;
    int m0 = blockIdx.y * 64, n0 = blockIdx.x * 64;

    float acc[4][4] = {};

    for (int k0 = 0; k0 < K; k0 += 16) {
#pragma unroll
        for (int t = 0; t < 4; t++) {
            int idx = tid + t * 256;
            int r = idx >> 4, kk = idx & 15;
            int gm = m0 + r, gk = k0 + kk;
            As[r][kk] = (gm < M && gk < K) ? A[(size_t)gm * lda + gk] : 0.f;
        }
        if (TRANS_B) {
#pragma unroll
            for (int t = 0; t < 4; t++) {
                int idx = tid + t * 256;
                int r = idx >> 4, kk = idx & 15;
                int gn = n0 + r, gk = k0 + kk;
                Bs[r][kk] = (gn < Nn && gk < K) ? Bm[(size_t)gn * ldb + gk] : 0.f;
            }
        } else {
#pragma unroll
            for (int t = 0; t < 4; t++) {
                int idx = tid + t * 256;
                int cc = idx & 63, kk = idx >> 6;
                int gn = n0 + cc, gk = k0 + kk;
                Bs[cc][kk] = (gn < Nn && gk < K) ? Bm[(size_t)gk * ldb + gn] : 0.f;
            }
        }
        __syncthreads();
#pragma unroll
        for (int kk = 0; kk < 16; kk++) {
            float a[4], b[4];
#pragma unroll
            for (int i = 0; i < 4; i++) a[i] = As[ty + 16 * i][kk];
#pragma unroll
            for (int j = 0; j < 4; j++) b[j] = Bs[tx + 16 * j][kk];
#pragma unroll
            for (int i = 0; i < 4; i++)
#pragma unroll
                for (int j = 0; j < 4; j++)
                    acc[i][j] += a[i] * b[j];
        }
        __syncthreads();
    }

    float alpha = alphaC * (alphaPtr ? *alphaPtr : 1.f);
#pragma unroll
    for (int i = 0; i < 4; i++) {
        int gm = m0 + ty + 16 * i;
        if (gm >= M) continue;
#pragma unroll
        for (int j = 0; j < 4; j++) {
            int gn = n0 + tx + 16 * j;
            if (gn >= Nn) continue;
            float v = acc[i][j];
            if (bias) v += bias[gn];
            v *= alpha;
            size_t off = (size_t)gm * ldc + gn;
            if (accum) v += Cm[off];
            Cm[off] = v;
        }
    }
}

// ---------------- im2col patch gather ----------------
__global__ void gather_k(const float* __restrict__ smri, float* __restrict__ pat) {
    int idx = blockIdx.x * 256 + threadIdx.x;
    if (idx >= BQ * NPATCH * 512) return;
    int kk = idx & 511;
    int m  = idx >> 9;
    int bb = m / NPATCH, p = m % NPATCH;
    int gx = p / (GD * GD), gy = (p / GD) % GD, gz = p % GD;
    int i = kk >> 6, j = (kk >> 3) & 7, kq = kk & 7;
    pat[idx] = smri[(((size_t)bb * IMG + gx * PSZ + i) * IMG + gy * PSZ + j) * IMG
                    + gz * PSZ + kq];
}

// ---------------- LN(patch embed) + cls + pos_embed ----------------
__global__ void ln_pos_k(const float* __restrict__ tmp, const float* __restrict__ g,
                         const float* __restrict__ b, const float* __restrict__ cls,
                         const float* __restrict__ pos, float* __restrict__ x)
{
    int bt = blockIdx.x;
    int bb = bt / NTOK, t = bt % NTOK;
    int tid = threadIdx.x;
    float* out = x + (size_t)bt * CDIM;
    const float* pp = pos + (size_t)t * CDIM;
    if (t == 0) {
        for (int c = tid; c < CDIM; c += 256) out[c] = cls[c] + pp[c];
        return;
    }
    const float* row = tmp + ((size_t)bb * NPATCH + (t - 1)) * CDIM;
    __shared__ float red[256];
    float s = 0.f, s2 = 0.f;
    for (int c = tid; c < CDIM; c += 256) { float v = row[c]; s += v; s2 += v * v; }
    red[tid] = s; __syncthreads();
    for (int st = 128; st > 0; st >>= 1) { if (tid < st) red[tid] += red[tid + st]; __syncthreads(); }
    float mean = red[0] / CDIM; __syncthreads();
    red[tid] = s2; __syncthreads();
    for (int st = 128; st > 0; st >>= 1) { if (tid < st) red[tid] += red[tid + st]; __syncthreads(); }
    float var = red[0] / CDIM - mean * mean;
    float inv = rsqrtf(var + 1e-5f);
    for (int c = tid; c < CDIM; c += 256)
        out[c] = (row[c] - mean) * inv * g[c] + b[c] + pp[c];
}

// ---------------- row softmax over scores (region bias is softmax-invariant) ------
__global__ void softmax_rows(float* __restrict__ S) {
    __shared__ float buf[NTOK];
    __shared__ float red[256];
    size_t row = blockIdx.x;
    float* p = S + row * (size_t)NTOK;
    int tid = threadIdx.x;
    float mx = -1e30f;
    for (int i = tid; i < NTOK; i += 256) { float v = p[i]; buf[i] = v; mx = fmaxf(mx, v); }
    red[tid] = mx; __syncthreads();
    for (int st = 128; st > 0; st >>= 1) { if (tid < st) red[tid] = fmaxf(red[tid], red[tid + st]); __syncthreads(); }
    mx = red[0]; __syncthreads();
    float sm = 0.f;
    for (int i = tid; i < NTOK; i += 256) { float e = __expf(buf[i] - mx); buf[i] = e; sm += e; }
    red[tid] = sm; __syncthreads();
    for (int st = 128; st > 0; st >>= 1) { if (tid < st) red[tid] += red[tid + st]; __syncthreads(); }
    float inv = 1.f / red[0];
    for (int i = tid; i < NTOK; i += 256) p[i] = buf[i] * inv;
}

// ---------------- CLS-query attention for a branch (q only at token 0) ------------
__global__ void cls_attn_k(const float* __restrict__ q0, const float* __restrict__ kv,
                           float* __restrict__ oc)
{
    int z = blockIdx.x;
    int bb = z / NHEAD, hh = z % NHEAD;
    __shared__ float sS[NTOK];
    __shared__ float sq[HD];
    __shared__ float red[128];
    int tid = threadIdx.x;
    for (int j = tid; j < HD; j += 128) sq[j] = q0[bb * CDIM + hh * HD + j];
    __syncthreads();
    const float scale = 0.10206207261596577f;  // 1/sqrt(96)
    float mx = -1e30f;
    for (int t = tid; t < NTOK; t += 128) {
        const float* kr = kv + ((size_t)(bb * NTOK + t)) * (2 * CDIM) + hh * HD;
        float s = 0.f;
        for (int j = 0; j < HD; j++) s += sq[j] * kr[j];
        s *= scale;
        sS[t] = s;
        mx = fmaxf(mx, s);
    }
    red[tid] = mx; __syncthreads();
    for (int st = 64; st > 0; st >>= 1) { if (tid < st) red[tid] = fmaxf(red[tid], red[tid + st]); __syncthreads(); }
    mx = red[0]; __syncthreads();
    float sm = 0.f;
    for (int t = tid; t < NTOK; t += 128) { float e = __expf(sS[t] - mx); sS[t] = e; sm += e; }
    red[tid] = sm; __syncthreads();
    for (int st = 64; st > 0; st >>= 1) { if (tid < st) red[tid] += red[tid + st]; __syncthreads(); }
    float inv = 1.f / red[0];
    __syncthreads();
    if (tid < HD) {
        float acc = 0.f;
        for (int t = 0; t < NTOK; t++)
            acc += sS[t] * kv[((size_t)(bb * NTOK + t)) * (2 * CDIM) + CDIM + hh * HD + tid];
        oc[bb * CDIM + hh * HD + tid] = acc * inv;
    }
}

// ---------------- LN + head on CLS ----------------
__global__ void head_k(const float* __restrict__ fin, const float* __restrict__ g,
                       const float* __restrict__ b, const float* __restrict__ hw,
                       const float* __restrict__ hb, float* __restrict__ out)
{
    int bb = blockIdx.x;
    const float* row = fin + bb * CDIM;
    __shared__ float red[256];
    __shared__ float sn[CDIM];
    int tid = threadIdx.x;
    float s = 0.f, s2 = 0.f;
    for (int c = tid; c < CDIM; c += 256) { float v = row[c]; s += v; s2 += v * v; }
    red[tid] = s; __syncthreads();
    for (int st = 128; st > 0; st >>= 1) { if (tid < st) red[tid] += red[tid + st]; __syncthreads(); }
    float mean = red[0] / CDIM; __syncthreads();
    red[tid] = s2; __syncthreads();
    for (int st = 128; st > 0; st >>= 1) { if (tid < st) red[tid] += red[tid + st]; __syncthreads(); }
    float var = red[0] / CDIM - mean * mean;
    float inv = rsqrtf(var + 1e-5f);
    for (int c = tid; c < CDIM; c += 256) sn[c] = (row[c] - mean) * inv * g[c] + b[c];
    __syncthreads();
    if (tid < NCLS) {
        float acc = hb[tid];
        for (int c = 0; c < CDIM; c++) acc += sn[c] * hw[tid * CDIM + c];
        out[bb * NCLS + tid] = acc;
    }
}

// ---------------- host ----------------
static inline int cdiv(int a, int b) { return (a + b - 1) / b; }

static void gemm_nt(const float* A, const float* B, const float* bias, float* C,
                    int M, int Nn, int K, int lda, int ldb, int ldc,
                    size_t sAb = 0, size_t sAh = 0, size_t sBb = 0, size_t sBh = 0,
                    size_t sCb = 0, size_t sCh = 0, int nh = 1, int batches = 1,
                    float alphaC = 1.f, const float* alphaPtr = nullptr, int accum = 0)
{
    dim3 grid(cdiv(Nn, 64), cdiv(M, 64), batches);
    gemm_k<1><<<grid, 256>>>(A, B, bias, C, M, Nn, K, lda, ldb, ldc,
                             sAb, sAh, sBb, sBh, sCb, sCh, nh, alphaC, alphaPtr, accum);
}

static void gemm_nn(const float* A, const float* B, const float* bias, float* C,
                    int M, int Nn, int K, int lda, int ldb, int ldc,
                    size_t sAb, size_t sAh, size_t sBb, size_t sBh,
                    size_t sCb, size_t sCh, int nh, int batches)
{
    dim3 grid(cdiv(Nn, 64), cdiv(M, 64), batches);
    gemm_k<0><<<grid, 256>>>(A, B, bias, C, M, Nn, K, lda, ldb, ldc,
                             sAb, sAh, sBb, sBh, sCb, sCh, nh, 1.f, nullptr, 0);
}

extern "C" void kernel_launch(void* const* d_in, const int* in_sizes, int n_in,
                              void* d_out, int out_size)
{
    const float* smri     = (const float*)d_in[0];
    const float* conv_w   = (const float*)d_in[2];
    const float* conv_b   = (const float*)d_in[3];
    const float* pe_ln_g  = (const float*)d_in[4];
    const float* pe_ln_b  = (const float*)d_in[5];
    const float* q_w      = (const float*)d_in[6];
    const float* q_b      = (const float*)d_in[7];
    const float* k_w      = (const float*)d_in[8];
    const float* k_b      = (const float*)d_in[9];
    const float* v_w      = (const float*)d_in[10];
    const float* v_b      = (const float*)d_in[11];
    const float* loc_in_w = (const float*)d_in[13];
    const float* loc_in_b = (const float*)d_in[14];
    const float* loc_out_w= (const float*)d_in[15];
    const float* loc_out_b= (const float*)d_in[16];
    const float* glob_in_w = (const float*)d_in[17];
    const float* glob_in_b = (const float*)d_in[18];
    const float* glob_out_w= (const float*)d_in[19];
    const float* glob_out_b= (const float*)d_in[20];
    const float* w_local  = (const float*)d_in[21];
    const float* w_global = (const float*)d_in[22];
    const float* cls_tok  = (const float*)d_in[23];
    const float* pos_emb  = (const float*)d_in[24];
    const float* head_ln_g= (const float*)d_in[25];
    const float* head_ln_b= (const float*)d_in[26];
    const float* head_w   = (const float*)d_in[27];
    const float* head_b   = (const float*)d_in[28];
    float* out = (float*)d_out;

    float *pat, *tmp, *x, *q, *k, *v, *S, *x2, *kv, *q0, *oc, *fin;
    cudaGetSymbolAddress((void**)&pat, g_pat);
    cudaGetSymbolAddress((void**)&tmp, g_tmp);
    cudaGetSymbolAddress((void**)&x,   g_x);
    cudaGetSymbolAddress((void**)&q,   g_q);
    cudaGetSymbolAddress((void**)&k,   g_k);
    cudaGetSymbolAddress((void**)&v,   g_v);
    cudaGetSymbolAddress((void**)&S,   g_S);
    cudaGetSymbolAddress((void**)&x2,  g_x2);
    cudaGetSymbolAddress((void**)&kv,  g_kv);
    cudaGetSymbolAddress((void**)&q0,  g_q0);
    cudaGetSymbolAddress((void**)&oc,  g_oc);
    cudaGetSymbolAddress((void**)&fin, g_fin);

    const float scale = 0.10206207261596577f;   // 1/sqrt(96)
    const size_t sT = (size_t)NTOK * CDIM;      // per-batch token stride
    const size_t sSb = (size_t)NHEAD * NTOK * NTOK;
    const size_t sSh = (size_t)NTOK * NTOK;

    // 1) patch im2col + embed GEMM
    gather_k<<<cdiv(BQ * NPATCH * 512, 256), 256>>>(smri, pat);
    gemm_nt(pat, conv_w, conv_b, tmp, BQ * NPATCH, CDIM, 512, 512, 512, CDIM);

    // 2) LN + cls + pos
    ln_pos_k<<<BQ * NTOK, 256>>>(tmp, pe_ln_g, pe_ln_b, cls_tok, pos_emb, x);

    // 3) regional QKV projections
    gemm_nt(x, q_w, q_b, q, BQ * NTOK, CDIM, CDIM, CDIM, CDIM, CDIM);
    gemm_nt(x, k_w, k_b, k, BQ * NTOK, CDIM, CDIM, CDIM, CDIM, CDIM);
    gemm_nt(x, v_w, v_b, v, BQ * NTOK, CDIM, CDIM, CDIM, CDIM, CDIM);

    // 4) scores = scale * Q K^T  (region bias dropped: softmax-invariant)
    gemm_nt(q, k, nullptr, S, NTOK, NTOK, HD, CDIM, CDIM, NTOK,
            sT, HD, sT, HD, sSb, sSh, NHEAD, BQ * NHEAD, scale);

    // 5) softmax rows
    softmax_rows<<<BQ * NHEAD * NTOK, 256>>>(S);

    // 6) x2 = A @ V
    gemm_nn(S, v, nullptr, x2, NTOK, HD, NTOK, NTOK, CDIM, CDIM,
            sSb, sSh, sT, HD, sT, HD, NHEAD, BQ * NHEAD);

    // 7) branches: only CLS output matters -> K,V for all tokens, Q at token 0
    // local
    gemm_nt(x2, loc_in_w + (size_t)CDIM * CDIM, loc_in_b + CDIM, kv,
            BQ * NTOK, 2 * CDIM, CDIM, CDIM, CDIM, 2 * CDIM);
    gemm_nt(x2, loc_in_w, loc_in_b, q0, BQ, CDIM, CDIM, (int)sT, CDIM, CDIM);
    cls_attn_k<<<BQ * NHEAD, 128>>>(q0, kv, oc);
    gemm_nt(oc, loc_out_w, loc_out_b, fin, BQ, CDIM, CDIM, CDIM, CDIM, CDIM,
            0, 0, 0, 0, 0, 0, 1, 1, 1.f, w_local, /*accum=*/0);
    // global
    gemm_nt(x2, glob_in_w + (size_t)CDIM * CDIM, glob_in_b + CDIM, kv,
            BQ * NTOK, 2 * CDIM, CDIM, CDIM, CDIM, 2 * CDIM);
    gemm_nt(x2, glob_in_w, glob_in_b, q0, BQ, CDIM, CDIM, (int)sT, CDIM, CDIM);
    cls_attn_k<<<BQ * NHEAD, 128>>>(q0, kv, oc);
    gemm_nt(oc, glob_out_w, glob_out_b, fin, BQ, CDIM, CDIM, CDIM, CDIM, CDIM,
            0, 0, 0, 0, 0, 0, 1, 1, 1.f, w_global, /*accum=*/1);

    // 8) head on CLS
    head_k<<<BQ, 256>>>(fin, head_ln_g, head_ln_b, head_w, head_b, out);
}